// round 9
// baseline (speedup 1.0000x reference)
#include <cuda_runtime.h>
#include <cuda_bf16.h>

typedef unsigned long long u64;
typedef unsigned int u32;

// ---------- helpers ----------
__device__ __forceinline__ u64 pk(float a, float b) {
    u64 r; asm("mov.b64 %0, {%1,%2};" : "=l"(r) : "f"(a), "f"(b)); return r;
}
__device__ __forceinline__ u64 fma2(u64 a, u64 b, u64 c) {
    u64 d; asm("fma.rn.f32x2 %0, %1, %2, %3;" : "=l"(d) : "l"(a), "l"(b), "l"(c)); return d;
}
__device__ __forceinline__ float2 upk(u64 a) {
    float x, y; asm("mov.b64 {%0,%1}, %2;" : "=f"(x), "=f"(y) : "l"(a));
    return make_float2(x, y);
}
__device__ __forceinline__ float lrelu(float x) { return fmaxf(x, 0.01f * x); }
__device__ __forceinline__ float softplus_f(float x) {
    return fmaxf(x, 0.0f) + log1pf(expf(-fabsf(x)));
}
__device__ __forceinline__ u32 smem_u32(const void* p) {
    u32 a; asm("{ .reg .u64 t; cvta.to.shared.u64 t, %1; cvt.u32.u64 %0, t; }"
               : "=r"(a) : "l"(p)); return a;
}
// pack two f32 -> bf16x2: low half = lo_val, high half = hi_val
__device__ __forceinline__ u32 cvt_bf2(float lo_val, float hi_val) {
    u32 r; asm("cvt.rn.bf16x2.f32 %0, %1, %2;" : "=r"(r) : "f"(hi_val), "f"(lo_val));
    return r;
}
__device__ __forceinline__ float bf_lo_f(u32 v) { return __uint_as_float(v << 16); }
__device__ __forceinline__ float bf_hi_f(u32 v) { return __uint_as_float(v & 0xffff0000u); }

__device__ __forceinline__ void ldsm4(u32* r, u32 addr) {
    asm volatile("ldmatrix.sync.aligned.m8n8.x4.shared.b16 {%0,%1,%2,%3}, [%4];"
                 : "=r"(r[0]), "=r"(r[1]), "=r"(r[2]), "=r"(r[3]) : "r"(addr));
}
__device__ __forceinline__ void mma_bf16(float* d, const u32* a, const u32* b) {
    asm volatile(
        "mma.sync.aligned.m16n8k16.row.col.f32.bf16.bf16.f32 "
        "{%0,%1,%2,%3}, {%4,%5,%6,%7}, {%8,%9}, {%0,%1,%2,%3};"
        : "+f"(d[0]), "+f"(d[1]), "+f"(d[2]), "+f"(d[3])
        : "r"(a[0]), "r"(a[1]), "r"(a[2]), "r"(a[3]), "r"(b[0]), "r"(b[1]));
}
__device__ __forceinline__ u32 swz(u32 off) { return off ^ ((off >> 3) & 0x70); }

#define TPB 128
#define GRIDN 444   // 148 SMs * 3 CTAs

__global__ __launch_bounds__(TPB, 3)
void dln_mma_kernel(const float4* __restrict__ x,
                    const float4* __restrict__ W1, const float* __restrict__ b1,
                    const float* __restrict__ W2f, const float* __restrict__ b2,
                    const float* __restrict__ W_Ld, const float* __restrict__ b_Ld,
                    const float* __restrict__ W_Lo, const float* __restrict__ b_Lo,
                    float4* __restrict__ out, int n, int nwt)
{
    // per-warp A staging: 32 rows x 64 cols bf16 = 4KB hi + 4KB lo
    __shared__ __align__(128) unsigned char sA[4][2][4096];
    __shared__ u64    sBlo[8 * 4 * 32];    // B-lo fragments [nt*4+kc][lane]
    __shared__ float4 sW1[64];
    __shared__ float  sB1[64];
    __shared__ u64    sB2p[32];            // (b2[2i], b2[2i+1])
    __shared__ u64    sW3x[32], sW3y[32], sW3z[32];
    __shared__ float  sB3[3];

    const int tid = threadIdx.x;
    const int wid = tid >> 5;
    const int lane = tid & 31;
    const int g = lane >> 2;     // group id (row within 8)
    const int t = lane & 3;      // thread in group (col pair)

    // ---- stage small weights ----
    for (int i = tid; i < 64; i += TPB) {
        sW1[i] = W1[i];
        sB1[i] = b1[i];
    }
    for (int i = tid; i < 32; i += TPB) {
        sB2p[i] = pk(b2[2 * i],          b2[2 * i + 1]);
        sW3x[i] = pk(W_Ld[2 * i],        W_Ld[2 * i + 1]);
        sW3y[i] = pk(W_Ld[64 + 2 * i],   W_Ld[64 + 2 * i + 1]);
        sW3z[i] = pk(W_Lo[2 * i],        W_Lo[2 * i + 1]);
    }
    if (tid == 0) { sB3[0] = b_Ld[0]; sB3[1] = b_Ld[1]; sB3[2] = b_Lo[0]; }

    // ---- build B fragments: hi in registers, lo in SMEM table ----
    // B[k][n] = W2[n][k];  frag (nt,kc): b0={B[k0][n],B[k0+1][n]}, b1={B[k0+8][n],B[k0+9][n]}
    // with n = nt*8+g, k0 = kc*16+2t
    u32 bhi[8][4][2];
#pragma unroll
    for (int nt = 0; nt < 8; nt++) {
#pragma unroll
        for (int kc = 0; kc < 4; kc++) {
            const int nn = nt * 8 + g;
            const int k0 = kc * 16 + 2 * t;
            const float f0 = W2f[nn * 64 + k0];
            const float f1 = W2f[nn * 64 + k0 + 1];
            const float f2 = W2f[nn * 64 + k0 + 8];
            const float f3 = W2f[nn * 64 + k0 + 9];
            const u32 h0 = cvt_bf2(f0, f1);
            const u32 h1 = cvt_bf2(f2, f3);
            bhi[nt][kc][0] = h0;
            bhi[nt][kc][1] = h1;
            if (wid == 0) {
                const u32 l0 = cvt_bf2(f0 - bf_lo_f(h0), f1 - bf_hi_f(h0));
                const u32 l1 = cvt_bf2(f2 - bf_lo_f(h1), f3 - bf_hi_f(h1));
                sBlo[(nt * 4 + kc) * 32 + lane] = ((u64)l1 << 32) | (u64)l0;
            }
        }
    }
    __syncthreads();   // one-time: weights + sBlo visible to all warps

    unsigned char* myAhi = sA[wid][0];
    unsigned char* myAlo = sA[wid][1];
    const u32 aHiB = smem_u32(myAhi);
    const u32 aLoB = smem_u32(myAlo);
    // ldmatrix lane address pieces: row = mt*16 + (lane&15), byte col = kc*32 + (lane>>4)*16
    const int lrow = (lane & 15);
    const int lcol16 = (lane >> 4) * 16;

    const int TOTW = GRIDN * 4;            // total warps chip-wide
    int wt = blockIdx.x * 4 + wid;         // warp-tile index (32 rows each)

    float4 xv = make_float4(0.f, 0.f, 0.f, 0.f);
    if (wt < nwt) {
        const int r = wt * 32 + lane;
        if (r < n) xv = x[r];
    }

    for (; wt < nwt; wt += TOTW) {
        // ---- layer 1 (FFMA): this lane's row -> bf16 hi/lo into warp staging ----
        {
            const u64 q01 = pk(xv.x, xv.y), q23 = pk(xv.z, xv.w);
#pragma unroll
            for (int it = 0; it < 8; it++) {          // 8 cols per iteration, 64 total
                u32 hi4[4], lo4[4];
#pragma unroll
                for (int p = 0; p < 4; p++) {
                    const int j0 = it * 8 + 2 * p;
                    const float4 w0 = sW1[j0];
                    const float4 w1 = sW1[j0 + 1];
                    u64 a0 = fma2(pk(w0.x, w0.y), q01, pk(sB1[j0], 0.f));
                    a0     = fma2(pk(w0.z, w0.w), q23, a0);
                    u64 a1 = fma2(pk(w1.x, w1.y), q01, pk(sB1[j0 + 1], 0.f));
                    a1     = fma2(pk(w1.z, w1.w), q23, a1);
                    const float2 r0 = upk(a0), r1 = upk(a1);
                    const float h0 = lrelu(r0.x + r0.y);
                    const float h1 = lrelu(r1.x + r1.y);
                    const u32 hp = cvt_bf2(h0, h1);
                    hi4[p] = hp;
                    lo4[p] = cvt_bf2(h0 - bf_lo_f(hp), h1 - bf_hi_f(hp));
                }
                const u32 off = swz((u32)(lane * 128 + it * 16));
                *reinterpret_cast<uint4*>(myAhi + off) = make_uint4(hi4[0], hi4[1], hi4[2], hi4[3]);
                *reinterpret_cast<uint4*>(myAlo + off) = make_uint4(lo4[0], lo4[1], lo4[2], lo4[3]);
            }
        }
        // prefetch next tile's x
        {
            const int ntile = wt + TOTW;
            float4 xn = make_float4(0.f, 0.f, 0.f, 0.f);
            if (ntile < nwt) {
                const int r2 = ntile * 32 + lane;
                if (r2 < n) xn = x[r2];
            }
            xv = xn;
        }
        __syncwarp();   // staging visible within warp

        // ---- MMA: two 16-row m-tiles from this warp's staging ----
#pragma unroll
        for (int mt = 0; mt < 2; mt++) {
            float acc[8][4];
#pragma unroll
            for (int nt = 0; nt < 8; nt++) {
                acc[nt][0] = 0.f; acc[nt][1] = 0.f; acc[nt][2] = 0.f; acc[nt][3] = 0.f;
            }
#pragma unroll
            for (int kc = 0; kc < 4; kc++) {
                const u32 off = swz((u32)((mt * 16 + lrow) * 128 + kc * 32 + lcol16));
                u32 ahi[4], alo[4];
                ldsm4(ahi, aHiB + off);
                ldsm4(alo, aLoB + off);
                // preload all B-lo fragments for this kc
                u32 bl[8][2];
#pragma unroll
                for (int nt = 0; nt < 8; nt++) {
                    const u64 v = sBlo[(nt * 4 + kc) * 32 + lane];
                    bl[nt][0] = (u32)v; bl[nt][1] = (u32)(v >> 32);
                }
                // three 8-wide passes: adjacent MMAs hit different accumulators
#pragma unroll
                for (int nt = 0; nt < 8; nt++) mma_bf16(acc[nt], ahi, bhi[nt][kc]);
#pragma unroll
                for (int nt = 0; nt < 8; nt++) mma_bf16(acc[nt], ahi, bl[nt]);
#pragma unroll
                for (int nt = 0; nt < 8; nt++) mma_bf16(acc[nt], alo, bhi[nt][kc]);
            }

            // ---- epilogue for this m-tile ----
            u64 D0a = 0ULL, D1a = 0ULL, Oa = 0ULL;
            u64 D0b = 0ULL, D1b = 0ULL, Ob = 0ULL;
#pragma unroll
            for (int nt = 0; nt < 8; nt++) {
                const int i = nt * 4 + t;
                const float2 bb = upk(sB2p[i]);
                const u64 ha = pk(lrelu(acc[nt][0] + bb.x), lrelu(acc[nt][1] + bb.y));
                const u64 hb = pk(lrelu(acc[nt][2] + bb.x), lrelu(acc[nt][3] + bb.y));
                const u64 wx = sW3x[i], wy = sW3y[i], wz = sW3z[i];
                D0a = fma2(wx, ha, D0a); D1a = fma2(wy, ha, D1a); Oa = fma2(wz, ha, Oa);
                D0b = fma2(wx, hb, D0b); D1b = fma2(wy, hb, D1b); Ob = fma2(wz, hb, Ob);
            }
            float v0, v1, v2, v3, v4, v5;
            { const float2 e = upk(D0a); v0 = e.x + e.y; }
            { const float2 e = upk(D1a); v1 = e.x + e.y; }
            { const float2 e = upk(Oa);  v2 = e.x + e.y; }
            { const float2 e = upk(D0b); v3 = e.x + e.y; }
            { const float2 e = upk(D1b); v4 = e.x + e.y; }
            { const float2 e = upk(Ob);  v5 = e.x + e.y; }
            v0 += __shfl_xor_sync(0xffffffffu, v0, 1); v0 += __shfl_xor_sync(0xffffffffu, v0, 2);
            v1 += __shfl_xor_sync(0xffffffffu, v1, 1); v1 += __shfl_xor_sync(0xffffffffu, v1, 2);
            v2 += __shfl_xor_sync(0xffffffffu, v2, 1); v2 += __shfl_xor_sync(0xffffffffu, v2, 2);
            v3 += __shfl_xor_sync(0xffffffffu, v3, 1); v3 += __shfl_xor_sync(0xffffffffu, v3, 2);
            v4 += __shfl_xor_sync(0xffffffffu, v4, 1); v4 += __shfl_xor_sync(0xffffffffu, v4, 2);
            v5 += __shfl_xor_sync(0xffffffffu, v5, 1); v5 += __shfl_xor_sync(0xffffffffu, v5, 2);

            if (t == 0) {
                const int rowA = wt * 32 + mt * 16 + g;
                const int rowB = rowA + 8;
                if (rowA < n) {
                    const float d0 = softplus_f(v0 + sB3[0]);
                    const float d1 = softplus_f(v1 + sB3[1]);
                    const float lo = v2 + sB3[2];
                    const float od = d0 * lo;
                    out[rowA] = make_float4(fmaf(d0, d0, 1e-9f), od, od,
                                            fmaf(lo, lo, fmaf(d1, d1, 1e-9f)));
                }
                if (rowB < n) {
                    const float d0 = softplus_f(v3 + sB3[0]);
                    const float d1 = softplus_f(v4 + sB3[1]);
                    const float lo = v5 + sB3[2];
                    const float od = d0 * lo;
                    out[rowB] = make_float4(fmaf(d0, d0, 1e-9f), od, od,
                                            fmaf(lo, lo, fmaf(d1, d1, 1e-9f)));
                }
            }
        }
        __syncwarp();   // all lanes done reading staging before next overwrite
    }
}

extern "C" void kernel_launch(void* const* d_in, const int* in_sizes, int n_in,
                              void* d_out, int out_size)
{
    const float4* x    = (const float4*)d_in[0];
    const float4* W1   = (const float4*)d_in[1];
    const float*  b1   = (const float*)d_in[2];
    const float*  W2   = (const float*)d_in[3];
    const float*  b2   = (const float*)d_in[4];
    const float*  W_Ld = (const float*)d_in[5];
    const float*  b_Ld = (const float*)d_in[6];
    const float*  W_Lo = (const float*)d_in[7];
    const float*  b_Lo = (const float*)d_in[8];
    float4* out = (float4*)d_out;

    const int n = in_sizes[0] / 4;                  // rows
    const int nwt = (n + 31) / 32;                  // 32-row warp-tiles
    int grid = (nwt + 3) / 4;
    if (grid > GRIDN) grid = GRIDN;
    dln_mma_kernel<<<grid, TPB>>>(x, W1, b1, W2, b2, W_Ld, b_Ld, W_Lo, b_Lo,
                                  out, n, nwt);
}

// round 12
// speedup vs baseline: 1.1521x; 1.1521x over previous
#include <cuda_runtime.h>
#include <cuda_bf16.h>

typedef unsigned long long u64;
typedef unsigned int u32;

// ---------- helpers ----------
__device__ __forceinline__ u64 pk(float a, float b) {
    u64 r; asm("mov.b64 %0, {%1,%2};" : "=l"(r) : "f"(a), "f"(b)); return r;
}
__device__ __forceinline__ u64 fma2(u64 a, u64 b, u64 c) {
    u64 d; asm("fma.rn.f32x2 %0, %1, %2, %3;" : "=l"(d) : "l"(a), "l"(b), "l"(c)); return d;
}
__device__ __forceinline__ float2 upk(u64 a) {
    float x, y; asm("mov.b64 {%0,%1}, %2;" : "=f"(x), "=f"(y) : "l"(a));
    return make_float2(x, y);
}
__device__ __forceinline__ float lrelu(float x) { return fmaxf(x, 0.01f * x); }
__device__ __forceinline__ float softplus_f(float x) {
    return fmaxf(x, 0.0f) + log1pf(expf(-fabsf(x)));
}
// pack two f32 -> bf16x2: low half = first arg, high half = second arg
__device__ __forceinline__ u32 cvt_bf2(float lo_val, float hi_val) {
    u32 r; asm("cvt.rn.bf16x2.f32 %0, %1, %2;" : "=r"(r) : "f"(hi_val), "f"(lo_val));
    return r;
}
__device__ __forceinline__ float bf_lo_f(u32 v) { return __uint_as_float(v << 16); }
__device__ __forceinline__ float bf_hi_f(u32 v) { return __uint_as_float(v & 0xffff0000u); }

__device__ __forceinline__ void mma_k16(float* d, const u32* a, const u32* b) {
    asm volatile(
        "mma.sync.aligned.m16n8k16.row.col.f32.bf16.bf16.f32 "
        "{%0,%1,%2,%3}, {%4,%5,%6,%7}, {%8,%9}, {%0,%1,%2,%3};"
        : "+f"(d[0]), "+f"(d[1]), "+f"(d[2]), "+f"(d[3])
        : "r"(a[0]), "r"(a[1]), "r"(a[2]), "r"(a[3]), "r"(b[0]), "r"(b[1]));
}
__device__ __forceinline__ void mma_k8(float* d, u32 a0, u32 a1, u32 b0) {
    asm volatile(
        "mma.sync.aligned.m16n8k8.row.col.f32.bf16.bf16.f32 "
        "{%0,%1,%2,%3}, {%4,%5}, {%6}, {%0,%1,%2,%3};"
        : "+f"(d[0]), "+f"(d[1]), "+f"(d[2]), "+f"(d[3])
        : "r"(a0), "r"(a1), "r"(b0));
}

#define TPB 128
#define GRIDN 296   // 148 SMs * 2 CTAs

__global__ __launch_bounds__(TPB, 2)
void dln_mma_kernel(const float* __restrict__ xf,
                    const float4* __restrict__ W1, const float* __restrict__ b1,
                    const float* __restrict__ W2f, const float* __restrict__ b2,
                    const float* __restrict__ W_Ld, const float* __restrict__ b_Ld,
                    const float* __restrict__ W_Lo, const float* __restrict__ b_Lo,
                    float4* __restrict__ out, int n, int nwt)
{
    __shared__ u64   sBlo[8 * 4 * 32];   // W2-lo fragments [nt*4+kc][lane]
    __shared__ u64   sB1p[32];           // (b1[2i], b1[2i+1])
    __shared__ u64   sB2p[32];           // (b2[2i], b2[2i+1])
    __shared__ u64   sW3x[32];           // W_Ld row0 pairs
    __shared__ u64   sW3y[32];           // W_Ld row1 pairs
    __shared__ u64   sW3z[32];           // W_Lo pairs
    __shared__ float sB3[3];

    const int tid = threadIdx.x;
    const int wid = tid >> 5;
    const int lane = tid & 31;
    const int g = lane >> 2;     // row-in-8
    const int t = lane & 3;      // col-pair selector

    // ---- stage tables ----
    for (int i = tid; i < 32; i += TPB) {
        sB1p[i] = pk(b1[2 * i], b1[2 * i + 1]);
        sB2p[i] = pk(b2[2 * i], b2[2 * i + 1]);
        sW3x[i] = pk(W_Ld[2 * i],      W_Ld[2 * i + 1]);
        sW3y[i] = pk(W_Ld[64 + 2 * i], W_Ld[64 + 2 * i + 1]);
        sW3z[i] = pk(W_Lo[2 * i],      W_Lo[2 * i + 1]);
    }
    if (tid == 0) { sB3[0] = b_Ld[0]; sB3[1] = b_Ld[1]; sB3[2] = b_Lo[0]; }

    // ---- W2 (layer-2 B): hi in regs, lo in SMEM ----
    // frag (nt,kc): b0={B[k0][n],B[k0+1][n]}, b1={B[k0+8][n],B[k0+9][n]}, n=nt*8+g, k0=kc*16+2t
    u32 bhi[8][4][2];
#pragma unroll
    for (int nt = 0; nt < 8; nt++) {
#pragma unroll
        for (int kc = 0; kc < 4; kc++) {
            const int nn = nt * 8 + g;
            const int k0 = kc * 16 + 2 * t;
            const float f0 = W2f[nn * 64 + k0];
            const float f1 = W2f[nn * 64 + k0 + 1];
            const float f2 = W2f[nn * 64 + k0 + 8];
            const float f3 = W2f[nn * 64 + k0 + 9];
            const u32 h0 = cvt_bf2(f0, f1);
            const u32 h1 = cvt_bf2(f2, f3);
            bhi[nt][kc][0] = h0;
            bhi[nt][kc][1] = h1;
            if (wid == 0) {
                const u32 l0 = cvt_bf2(f0 - bf_lo_f(h0), f1 - bf_hi_f(h0));
                const u32 l1 = cvt_bf2(f2 - bf_lo_f(h1), f3 - bf_hi_f(h1));
                sBlo[(nt * 4 + kc) * 32 + lane] = ((u64)l1 << 32) | (u64)l0;
            }
        }
    }

    // ---- W1 (layer-1 B, k<=4 so one k8 chunk): hi+lo in regs ----
    // b0 = {W1[n][2t], W1[n][2t+1]} for t<2, zero otherwise; n = nt*8+g
    u32 w1hi[8], w1lo[8];
#pragma unroll
    for (int nt = 0; nt < 8; nt++) {
        w1hi[nt] = 0u; w1lo[nt] = 0u;
        if (t < 2) {
            const float4 w = W1[nt * 8 + g];
            const float f0 = (t == 0) ? w.x : w.z;
            const float f1 = (t == 0) ? w.y : w.w;
            const u32 h = cvt_bf2(f0, f1);
            w1hi[nt] = h;
            w1lo[nt] = cvt_bf2(f0 - bf_lo_f(h), f1 - bf_hi_f(h));
        }
    }
    __syncwarp();
    __syncthreads();

    const int TOTW = GRIDN * 4;
    int wt = blockIdx.x * 4 + wid;           // 32-row warp-tile index

    for (; wt < nwt; wt += TOTW) {
#pragma unroll
        for (int mt = 0; mt < 2; mt++) {
            const int r0 = wt * 32 + mt * 16 + g;
            const int r1 = r0 + 8;

            // ---- x fragments (m16k8, k=4 real): hi/lo split ----
            float2 v0 = make_float2(0.f, 0.f), v1 = make_float2(0.f, 0.f);
            if (t < 2) {
                const float2* x2 = (const float2*)xf;
                if (r0 < n) v0 = x2[r0 * 2 + t];
                if (r1 < n) v1 = x2[r1 * 2 + t];
            }
            const u32 a0h = cvt_bf2(v0.x, v0.y);
            const u32 a0l = cvt_bf2(v0.x - bf_lo_f(a0h), v0.y - bf_hi_f(a0h));
            const u32 a1h = cvt_bf2(v1.x, v1.y);
            const u32 a1l = cvt_bf2(v1.x - bf_lo_f(a1h), v1.y - bf_hi_f(a1h));

            // ---- layer-1 MMA: l1 = x @ W1^T (3 passes) ----
            float l1[8][4];
#pragma unroll
            for (int nt = 0; nt < 8; nt++) {
                l1[nt][0] = 0.f; l1[nt][1] = 0.f; l1[nt][2] = 0.f; l1[nt][3] = 0.f;
            }
#pragma unroll
            for (int nt = 0; nt < 8; nt++) mma_k8(l1[nt], a0h, a1h, w1hi[nt]);
#pragma unroll
            for (int nt = 0; nt < 8; nt++) mma_k8(l1[nt], a0h, a1h, w1lo[nt]);
#pragma unroll
            for (int nt = 0; nt < 8; nt++) mma_k8(l1[nt], a0l, a1l, w1hi[nt]);

            // ---- bias + lrelu + hi/lo split -> layer-2 A fragments ----
            // ah[nt][0]: rows g, h1 cols nt*8+2t,2t+1 ; ah[nt][1]: rows g+8
            u32 ah[8][2], al[8][2];
#pragma unroll
            for (int nt = 0; nt < 8; nt++) {
                const float2 bb = upk(sB1p[nt * 4 + t]);
                const float h00 = lrelu(l1[nt][0] + bb.x);
                const float h01 = lrelu(l1[nt][1] + bb.y);
                const float h10 = lrelu(l1[nt][2] + bb.x);
                const float h11 = lrelu(l1[nt][3] + bb.y);
                const u32 p0 = cvt_bf2(h00, h01);
                const u32 p1 = cvt_bf2(h10, h11);
                ah[nt][0] = p0;
                ah[nt][1] = p1;
                al[nt][0] = cvt_bf2(h00 - bf_lo_f(p0), h01 - bf_hi_f(p0));
                al[nt][1] = cvt_bf2(h10 - bf_lo_f(p1), h11 - bf_hi_f(p1));
            }

            // ---- layer-2 MMA: acc = h1 @ W2^T (3 passes, K=64) ----
            float acc[8][4];
#pragma unroll
            for (int nt = 0; nt < 8; nt++) {
                acc[nt][0] = 0.f; acc[nt][1] = 0.f; acc[nt][2] = 0.f; acc[nt][3] = 0.f;
            }
#pragma unroll
            for (int kc = 0; kc < 4; kc++) {
                // A frag for this k-chunk comes from layer-1 n-tiles 2kc, 2kc+1
                u32 ahi4[4] = { ah[2 * kc][0], ah[2 * kc][1], ah[2 * kc + 1][0], ah[2 * kc + 1][1] };
                u32 alo4[4] = { al[2 * kc][0], al[2 * kc][1], al[2 * kc + 1][0], al[2 * kc + 1][1] };
                u32 bl[8][2];
#pragma unroll
                for (int nt = 0; nt < 8; nt++) {
                    const u64 v = sBlo[(nt * 4 + kc) * 32 + lane];
                    bl[nt][0] = (u32)v; bl[nt][1] = (u32)(v >> 32);
                }
#pragma unroll
                for (int nt = 0; nt < 8; nt++) mma_k16(acc[nt], ahi4, bhi[nt][kc]);
#pragma unroll
                for (int nt = 0; nt < 8; nt++) mma_k16(acc[nt], ahi4, bl[nt]);
#pragma unroll
                for (int nt = 0; nt < 8; nt++) mma_k16(acc[nt], alo4, bhi[nt][kc]);
            }

            // ---- epilogue: bias + lrelu + head + reduce + softplus + H ----
            u64 D0a = 0ULL, D1a = 0ULL, Oa = 0ULL;
            u64 D0b = 0ULL, D1b = 0ULL, Ob = 0ULL;
#pragma unroll
            for (int nt = 0; nt < 8; nt++) {
                const int i = nt * 4 + t;
                const float2 bb = upk(sB2p[i]);
                const u64 ha = pk(lrelu(acc[nt][0] + bb.x), lrelu(acc[nt][1] + bb.y));
                const u64 hb = pk(lrelu(acc[nt][2] + bb.x), lrelu(acc[nt][3] + bb.y));
                const u64 wx = sW3x[i], wy = sW3y[i], wz = sW3z[i];
                D0a = fma2(wx, ha, D0a); D1a = fma2(wy, ha, D1a); Oa = fma2(wz, ha, Oa);
                D0b = fma2(wx, hb, D0b); D1b = fma2(wy, hb, D1b); Ob = fma2(wz, hb, Ob);
            }
            float v0r, v1r, v2r, v3r, v4r, v5r;
            { const float2 e = upk(D0a); v0r = e.x + e.y; }
            { const float2 e = upk(D1a); v1r = e.x + e.y; }
            { const float2 e = upk(Oa);  v2r = e.x + e.y; }
            { const float2 e = upk(D0b); v3r = e.x + e.y; }
            { const float2 e = upk(D1b); v4r = e.x + e.y; }
            { const float2 e = upk(Ob);  v5r = e.x + e.y; }
            v0r += __shfl_xor_sync(0xffffffffu, v0r, 1); v0r += __shfl_xor_sync(0xffffffffu, v0r, 2);
            v1r += __shfl_xor_sync(0xffffffffu, v1r, 1); v1r += __shfl_xor_sync(0xffffffffu, v1r, 2);
            v2r += __shfl_xor_sync(0xffffffffu, v2r, 1); v2r += __shfl_xor_sync(0xffffffffu, v2r, 2);
            v3r += __shfl_xor_sync(0xffffffffu, v3r, 1); v3r += __shfl_xor_sync(0xffffffffu, v3r, 2);
            v4r += __shfl_xor_sync(0xffffffffu, v4r, 1); v4r += __shfl_xor_sync(0xffffffffu, v4r, 2);
            v5r += __shfl_xor_sync(0xffffffffu, v5r, 1); v5r += __shfl_xor_sync(0xffffffffu, v5r, 2);

            if (t == 0) {
                if (r0 < n) {
                    const float d0 = softplus_f(v0r + sB3[0]);
                    const float d1 = softplus_f(v1r + sB3[1]);
                    const float lo = v2r + sB3[2];
                    const float od = d0 * lo;
                    out[r0] = make_float4(fmaf(d0, d0, 1e-9f), od, od,
                                          fmaf(lo, lo, fmaf(d1, d1, 1e-9f)));
                }
                if (r1 < n) {
                    const float d0 = softplus_f(v3r + sB3[0]);
                    const float d1 = softplus_f(v4r + sB3[1]);
                    const float lo = v5r + sB3[2];
                    const float od = d0 * lo;
                    out[r1] = make_float4(fmaf(d0, d0, 1e-9f), od, od,
                                          fmaf(lo, lo, fmaf(d1, d1, 1e-9f)));
                }
            }
        }
    }
}

extern "C" void kernel_launch(void* const* d_in, const int* in_sizes, int n_in,
                              void* d_out, int out_size)
{
    const float*  x    = (const float*)d_in[0];
    const float4* W1   = (const float4*)d_in[1];
    const float*  b1   = (const float*)d_in[2];
    const float*  W2   = (const float*)d_in[3];
    const float*  b2   = (const float*)d_in[4];
    const float*  W_Ld = (const float*)d_in[5];
    const float*  b_Ld = (const float*)d_in[6];
    const float*  W_Lo = (const float*)d_in[7];
    const float*  b_Lo = (const float*)d_in[8];
    float4* out = (float4*)d_out;

    const int n = in_sizes[0] / 4;                  // rows
    const int nwt = (n + 31) / 32;                  // 32-row warp-tiles
    int grid = (nwt + 3) / 4;
    if (grid > GRIDN) grid = GRIDN;
    dln_mma_kernel<<<grid, TPB>>>(x, W1, b1, W2, b2, W_Ld, b_Ld, W_Lo, b_Lo,
                                  out, n, nwt);
}